// round 1
// baseline (speedup 1.0000x reference)
#include <cuda_runtime.h>

#define V_VOCAB 500000
#define D 128
#define M_MEM 1000
#define L_MEM 64
#define L_X 64
#define C_N 100
#define L_C 32
#define L_Y 32
#define N_SEQ (1 + M_MEM + 1 + C_N)   /* 1102 */
#define N_MEMS (M_MEM + 1)            /* 1001: [mems(0..999), xs] */
#define OUT_ROWS (1 + C_N)            /* 101 */
#define MAX_NORM 10.0f
#define RENORM_EPS 1e-7f
#define COS_EPS 1e-8f

// Scratch encodings: row 0 = xs, rows 1..1000 = mems, row 1001 = ys,
// rows 1002..1101 = cands.  564 KB device-global (no allocations allowed).
__device__ float g_enc[(size_t)N_SEQ * D];

__global__ __launch_bounds__(256) void encode_kernel(
    const int* __restrict__ xs, const int* __restrict__ mems,
    const int* __restrict__ ys, const int* __restrict__ cands,
    const float* __restrict__ lt, const float* __restrict__ freqs)
{
    int b = blockIdx.x;
    const int* seq;
    int L;
    if (b == 0)              { seq = xs;                          L = L_X; }
    else if (b <= M_MEM)     { seq = mems + (size_t)(b - 1) * L_MEM; L = L_MEM; }
    else if (b == M_MEM + 1) { seq = ys;                          L = L_Y; }
    else                     { seq = cands + (size_t)(b - M_MEM - 2) * L_C; L = L_C; }

    __shared__ int   sh_idx[L_MEM];
    __shared__ float sh_w[L_MEM];
    __shared__ float sh_wsq;
    __shared__ float sh_acc[8][D];

    int tid = threadIdx.x;
    if (tid == 0) sh_wsq = 0.0f;
    __syncthreads();

    if (tid < L) {
        int idx = seq[tid];
        sh_idx[tid] = idx;
        float f = freqs[idx];
        sh_w[tid] = f;
        atomicAdd(&sh_wsq, f * f);
    }
    __syncthreads();

    float inv_wnorm = 1.0f / sqrtf(sh_wsq);

    int warp = tid >> 5;
    int lane = tid & 31;

    float4 acc = make_float4(0.0f, 0.0f, 0.0f, 0.0f);
    for (int l = warp; l < L; l += 8) {
        int idx = sh_idx[l];
        float4 e = *reinterpret_cast<const float4*>(lt + (size_t)idx * D + lane * 4);
        float sq = e.x * e.x + e.y * e.y + e.z * e.z + e.w * e.w;
        #pragma unroll
        for (int o = 16; o > 0; o >>= 1)
            sq += __shfl_xor_sync(0xffffffffu, sq, o);
        float n = sqrtf(sq);
        float scale = (n > MAX_NORM) ? (MAX_NORM / (n + RENORM_EPS)) : 1.0f;
        float wl = sh_w[l] * inv_wnorm * scale;
        acc.x += wl * e.x;
        acc.y += wl * e.y;
        acc.z += wl * e.z;
        acc.w += wl * e.w;
    }

    sh_acc[warp][lane * 4 + 0] = acc.x;
    sh_acc[warp][lane * 4 + 1] = acc.y;
    sh_acc[warp][lane * 4 + 2] = acc.z;
    sh_acc[warp][lane * 4 + 3] = acc.w;
    __syncthreads();

    if (tid < D) {
        float s = 0.0f;
        #pragma unroll
        for (int w = 0; w < 8; w++) s += sh_acc[w][tid];
        g_enc[(size_t)b * D + tid] = s;
    }
}

__global__ __launch_bounds__(512) void attend_kernel(float* __restrict__ out)
{
    __shared__ float sh_x[D];
    __shared__ float sims[N_MEMS];
    __shared__ float red[16];
    __shared__ float sh_nx;
    __shared__ float sh_stat[2];
    __shared__ float part[4][D];

    int tid = threadIdx.x;
    int warp = tid >> 5;
    int lane = tid & 31;

    // ---- load xs encoding (row 0) ----
    if (tid < D) sh_x[tid] = g_enc[tid];
    __syncthreads();

    // ---- nx = max(||xs||, eps) ----
    if (tid < D) {
        float v = sh_x[tid];
        float sq = v * v;
        #pragma unroll
        for (int o = 16; o > 0; o >>= 1)
            sq += __shfl_xor_sync(0xffffffffu, sq, o);
        if (lane == 0) red[warp] = sq;
    }
    __syncthreads();
    if (tid == 0) {
        float s = red[0] + red[1] + red[2] + red[3];
        sh_nx = fmaxf(sqrtf(s), COS_EPS);
    }
    __syncthreads();
    float nx = sh_nx;

    // ---- cosine sims: one warp per memory row ----
    for (int i = warp; i < N_MEMS; i += 16) {
        int r = (i < M_MEM) ? (i + 1) : 0;
        float4 e = *reinterpret_cast<const float4*>(&g_enc[(size_t)r * D + lane * 4]);
        float4 x = *reinterpret_cast<const float4*>(&sh_x[lane * 4]);
        float dot = e.x * x.x + e.y * x.y + e.z * x.z + e.w * x.w;
        float sq  = e.x * e.x + e.y * e.y + e.z * e.z + e.w * e.w;
        #pragma unroll
        for (int o = 16; o > 0; o >>= 1) {
            dot += __shfl_xor_sync(0xffffffffu, dot, o);
            sq  += __shfl_xor_sync(0xffffffffu, sq, o);
        }
        if (lane == 0) {
            float nm = fmaxf(sqrtf(sq), COS_EPS);
            sims[i] = dot / (nx * nm);
        }
    }
    __syncthreads();

    // ---- softmax: max ----
    float lmx = -1e30f;
    for (int i = tid; i < N_MEMS; i += 512) lmx = fmaxf(lmx, sims[i]);
    #pragma unroll
    for (int o = 16; o > 0; o >>= 1)
        lmx = fmaxf(lmx, __shfl_xor_sync(0xffffffffu, lmx, o));
    if (lane == 0) red[warp] = lmx;
    __syncthreads();
    if (tid == 0) {
        float m = red[0];
        #pragma unroll
        for (int w = 1; w < 16; w++) m = fmaxf(m, red[w]);
        sh_stat[0] = m;
    }
    __syncthreads();
    float mx = sh_stat[0];

    // ---- softmax: exp + sum ----
    float lsum = 0.0f;
    for (int i = tid; i < N_MEMS; i += 512) {
        float e = expf(sims[i] - mx);
        sims[i] = e;
        lsum += e;
    }
    __syncthreads();
    #pragma unroll
    for (int o = 16; o > 0; o >>= 1)
        lsum += __shfl_xor_sync(0xffffffffu, lsum, o);
    if (lane == 0) red[warp] = lsum;
    __syncthreads();
    if (tid == 0) {
        float s = 0.0f;
        #pragma unroll
        for (int w = 0; w < 16; w++) s += red[w];
        sh_stat[1] = s;
    }
    __syncthreads();
    float inv_sum = 1.0f / sh_stat[1];

    // ---- lhs = (attn @ mems_enc): split i over 4 chunks for MLP ----
    {
        int d = tid & (D - 1);
        int chunk = tid >> 7;  // 0..3
        float acc = 0.0f;
        for (int i = chunk; i < N_MEMS; i += 4) {
            int r = (i < M_MEM) ? (i + 1) : 0;
            acc += sims[i] * g_enc[(size_t)r * D + d];
        }
        part[chunk][d] = acc;
    }
    __syncthreads();

    // ---- write xs_out (lhs broadcast to 101 rows) ----
    if (tid < D) {
        float lhs = (part[0][tid] + part[1][tid] + part[2][tid] + part[3][tid]) * inv_sum;
        #pragma unroll 4
        for (int row = 0; row < OUT_ROWS; row++)
            out[(size_t)row * D + tid] = lhs;
    }

    // ---- write ys_enc (enc rows 1001..1101) ----
    for (int j = tid; j < OUT_ROWS * D; j += 512)
        out[(size_t)OUT_ROWS * D + j] = g_enc[(size_t)N_MEMS * D + j];
}

extern "C" void kernel_launch(void* const* d_in, const int* in_sizes, int n_in,
                              void* d_out, int out_size) {
    const int*   xs    = (const int*)d_in[0];
    const int*   mems  = (const int*)d_in[1];
    const int*   ys    = (const int*)d_in[2];
    const int*   cands = (const int*)d_in[3];
    const float* lt    = (const float*)d_in[4];
    const float* freqs = (const float*)d_in[5];
    float* out = (float*)d_out;

    encode_kernel<<<N_SEQ, 256>>>(xs, mems, ys, cands, lt, freqs);
    attend_kernel<<<1, 512>>>(out);
}

// round 2
// speedup vs baseline: 1.8617x; 1.8617x over previous
#include <cuda_runtime.h>

#define V_VOCAB 500000
#define D 128
#define M_MEM 1000
#define L_MEM 64
#define L_X 64
#define C_N 100
#define L_C 32
#define L_Y 32
#define N_MEMS (M_MEM + 1)            /* 1001: [mems(0..999), xs] */
#define OUT_ROWS (1 + C_N)            /* 101 */
#define MAX_NORM 10.0f
#define RENORM_EPS 1e-7f
#define COS_EPS 1e-8f

// Scratch: row 0 = xs encoding, rows 1..1000 = mems encodings. 512.5 KB.
__device__ float g_enc[(size_t)N_MEMS * D];
// Raw cosine sims for the 1000 mems (xs-vs-xs sim computed in finalize).
__device__ float g_sims[M_MEM];

// ---------------------------------------------------------------------------
// Shared encode body: tf-idf weighted bag of (renormed) embeddings.
// 256 threads. Returns the per-dim result in *s_out for tid < D, and also
// writes it to dst[tid].
// ---------------------------------------------------------------------------
__device__ __forceinline__ float encode_body(
    const int* __restrict__ seq, int L,
    const float* __restrict__ lt, const float* __restrict__ freqs,
    float* __restrict__ dst)
{
    __shared__ int   sh_idx[L_MEM];
    __shared__ float sh_w[L_MEM];
    __shared__ float sh_wsq;
    __shared__ float sh_acc[8][D];

    int tid  = threadIdx.x;
    int warp = tid >> 5;
    int lane = tid & 31;

    if (tid == 0) sh_wsq = 0.0f;
    __syncthreads();

    if (tid < L) {
        int idx = seq[tid];
        sh_idx[tid] = idx;
        float f = freqs[idx];
        sh_w[tid] = f;
        atomicAdd(&sh_wsq, f * f);
    }
    __syncthreads();

    float inv_wnorm = rsqrtf(sh_wsq);

    float4 acc = make_float4(0.0f, 0.0f, 0.0f, 0.0f);
    for (int l = warp; l < L; l += 8) {
        int idx = sh_idx[l];
        float4 e = *reinterpret_cast<const float4*>(lt + (size_t)idx * D + lane * 4);
        float sq = e.x * e.x + e.y * e.y + e.z * e.z + e.w * e.w;
        #pragma unroll
        for (int o = 16; o > 0; o >>= 1)
            sq += __shfl_xor_sync(0xffffffffu, sq, o);
        float n = sqrtf(sq);
        float scale = (n > MAX_NORM) ? (MAX_NORM / (n + RENORM_EPS)) : 1.0f;
        float wl = sh_w[l] * inv_wnorm * scale;
        acc.x += wl * e.x;
        acc.y += wl * e.y;
        acc.z += wl * e.z;
        acc.w += wl * e.w;
    }

    sh_acc[warp][lane * 4 + 0] = acc.x;
    sh_acc[warp][lane * 4 + 1] = acc.y;
    sh_acc[warp][lane * 4 + 2] = acc.z;
    sh_acc[warp][lane * 4 + 3] = acc.w;
    __syncthreads();

    float s = 0.0f;
    if (tid < D) {
        #pragma unroll
        for (int w = 0; w < 8; w++) s += sh_acc[w][tid];
        dst[tid] = s;
    }
    return s;
}

// ---------------------------------------------------------------------------
// Kernel 0: encode xs -> g_enc row 0, encode ys -> out (row OUT_ROWS).
// ---------------------------------------------------------------------------
__global__ __launch_bounds__(256) void encode_head(
    const int* __restrict__ xs, const int* __restrict__ ys,
    const float* __restrict__ lt, const float* __restrict__ freqs,
    float* __restrict__ out)
{
    if (blockIdx.x == 0)
        encode_body(xs, L_X, lt, freqs, g_enc);
    else
        encode_body(ys, L_Y, lt, freqs, out + (size_t)OUT_ROWS * D);
}

// ---------------------------------------------------------------------------
// Kernel 1: blocks 0..999 encode mems -> g_enc rows 1..1000 AND compute the
// cosine sim against g_enc row 0 (written by kernel 0). Blocks 1000..1099
// encode cands directly into out rows OUT_ROWS+1 .. OUT_ROWS+100.
// ---------------------------------------------------------------------------
__global__ __launch_bounds__(256) void encode_main(
    const int* __restrict__ mems, const int* __restrict__ cands,
    const float* __restrict__ lt, const float* __restrict__ freqs,
    float* __restrict__ out)
{
    int b = blockIdx.x;
    int tid  = threadIdx.x;

    if (b >= M_MEM) {
        int c = b - M_MEM;
        encode_body(cands + (size_t)c * L_C, L_C, lt, freqs,
                    out + (size_t)(OUT_ROWS + 1 + c) * D);
        return;
    }

    float s = encode_body(mems + (size_t)b * L_MEM, L_MEM, lt, freqs,
                          g_enc + (size_t)(b + 1) * D);

    // --- cosine sim of this row vs xs encoding (g_enc row 0) ---
    __shared__ float red3[4][3];
    int warp = tid >> 5;
    int lane = tid & 31;
    if (tid < D) {
        float x  = g_enc[tid];
        float dot = s * x;
        float esq = s * s;
        float xsq = x * x;
        #pragma unroll
        for (int o = 16; o > 0; o >>= 1) {
            dot += __shfl_xor_sync(0xffffffffu, dot, o);
            esq += __shfl_xor_sync(0xffffffffu, esq, o);
            xsq += __shfl_xor_sync(0xffffffffu, xsq, o);
        }
        if (lane == 0) {
            red3[warp][0] = dot;
            red3[warp][1] = esq;
            red3[warp][2] = xsq;
        }
    }
    __syncthreads();
    if (tid == 0) {
        float dot = red3[0][0] + red3[1][0] + red3[2][0] + red3[3][0];
        float esq = red3[0][1] + red3[1][1] + red3[2][1] + red3[3][1];
        float xsq = red3[0][2] + red3[1][2] + red3[2][2] + red3[3][2];
        float nx = fmaxf(sqrtf(xsq), COS_EPS);
        float nm = fmaxf(sqrtf(esq), COS_EPS);
        g_sims[b] = dot / (nx * nm);
    }
}

// ---------------------------------------------------------------------------
// Kernel 2: softmax over 1001 sims + attention-weighted sum + output writes.
// Single block, 512 threads, MLP-friendly float4 loads.
// ---------------------------------------------------------------------------
__global__ __launch_bounds__(512) void finalize_kernel(float* __restrict__ out)
{
    __shared__ float sims[N_MEMS];
    __shared__ float red[16];
    __shared__ float sh_stat[2];
    __shared__ float part[16][D];
    __shared__ float sh_lhs[D];

    int tid  = threadIdx.x;
    int warp = tid >> 5;
    int lane = tid & 31;

    // --- load mem sims; compute xs-vs-xs sim (index 1000) ---
    for (int i = tid; i < M_MEM; i += 512) sims[i] = g_sims[i];
    if (tid < D) {
        float x = g_enc[tid];
        float sq = x * x;
        #pragma unroll
        for (int o = 16; o > 0; o >>= 1)
            sq += __shfl_xor_sync(0xffffffffu, sq, o);
        if (lane == 0) red[warp] = sq;
    }
    __syncthreads();
    if (tid == 0) {
        float sq = red[0] + red[1] + red[2] + red[3];
        float nx = fmaxf(sqrtf(sq), COS_EPS);
        sims[M_MEM] = sq / (nx * nx);
    }
    __syncthreads();

    // --- softmax max ---
    float lmx = -1e30f;
    for (int i = tid; i < N_MEMS; i += 512) lmx = fmaxf(lmx, sims[i]);
    #pragma unroll
    for (int o = 16; o > 0; o >>= 1)
        lmx = fmaxf(lmx, __shfl_xor_sync(0xffffffffu, lmx, o));
    if (lane == 0) red[warp] = lmx;
    __syncthreads();
    if (tid == 0) {
        float m = red[0];
        #pragma unroll
        for (int w = 1; w < 16; w++) m = fmaxf(m, red[w]);
        sh_stat[0] = m;
    }
    __syncthreads();
    float mx = sh_stat[0];

    // --- exp + sum ---
    float lsum = 0.0f;
    for (int i = tid; i < N_MEMS; i += 512) {
        float e = __expf(sims[i] - mx) ;
        // use precise expf to stay well inside 1e-3 rel-err:
        e = expf(sims[i] - mx);
        sims[i] = e;
        lsum += e;
    }
    #pragma unroll
    for (int o = 16; o > 0; o >>= 1)
        lsum += __shfl_xor_sync(0xffffffffu, lsum, o);
    if (lane == 0) red[warp] = lsum;
    __syncthreads();
    if (tid == 0) {
        float sm = 0.0f;
        #pragma unroll
        for (int w = 0; w < 16; w++) sm += red[w];
        sh_stat[1] = sm;
    }
    __syncthreads();
    float inv_sum = 1.0f / sh_stat[1];

    // --- weighted sum: 32 float4-lanes x 16 row-chunks, independent loads ---
    {
        int q = tid & 31;        // which float4 of the 128-dim row
        int chunk = tid >> 5;    // 0..15
        float4 acc = make_float4(0.0f, 0.0f, 0.0f, 0.0f);
        for (int i = chunk; i < N_MEMS; i += 16) {
            int r = (i < M_MEM) ? (i + 1) : 0;
            float4 e = *reinterpret_cast<const float4*>(&g_enc[(size_t)r * D + q * 4]);
            float w = sims[i];
            acc.x += w * e.x;
            acc.y += w * e.y;
            acc.z += w * e.z;
            acc.w += w * e.w;
        }
        part[chunk][q * 4 + 0] = acc.x;
        part[chunk][q * 4 + 1] = acc.y;
        part[chunk][q * 4 + 2] = acc.z;
        part[chunk][q * 4 + 3] = acc.w;
    }
    __syncthreads();

    if (tid < D) {
        float s = 0.0f;
        #pragma unroll
        for (int c = 0; c < 16; c++) s += part[c][tid];
        sh_lhs[tid] = s * inv_sum;
    }
    __syncthreads();

    // --- broadcast lhs to the 101 xs_out rows ---
    for (int j = tid; j < OUT_ROWS * D; j += 512)
        out[j] = sh_lhs[j & (D - 1)];
}

extern "C" void kernel_launch(void* const* d_in, const int* in_sizes, int n_in,
                              void* d_out, int out_size) {
    const int*   xs    = (const int*)d_in[0];
    const int*   mems  = (const int*)d_in[1];
    const int*   ys    = (const int*)d_in[2];
    const int*   cands = (const int*)d_in[3];
    const float* lt    = (const float*)d_in[4];
    const float* freqs = (const float*)d_in[5];
    float* out = (float*)d_out;

    encode_head<<<2, 256>>>(xs, ys, lt, freqs, out);
    encode_main<<<M_MEM + C_N, 256>>>(mems, cands, lt, freqs, out);
    finalize_kernel<<<1, 512>>>(out);
}